// round 3
// baseline (speedup 1.0000x reference)
#include <cuda_runtime.h>
#include <cstdint>

typedef unsigned long long u64;

#define NV    64          // vertices
#define NC    64          // channels (in = out)
#define LTOT  512
#define PADC  129         // float2 row stride (64*2 cols + 1 pad)
#define SM_CONST_FLOATS (4096 + 12288)           // A (64x64) + M0/1/2 (3x64x64)
#define BUF_F2          (64 * PADC)              // 8256 float2 per data buffer
#define SMEM_BYTES      (SM_CONST_FLOATS * 4 + 2 * BUF_F2 * 8)   // 197632

// Precomputed operators (device globals: no allocation allowed)
__device__ float g_a[64 * 64];        // row-normalized adjacency
__device__ float g_M[3 * 64 * 64];    // folded channel matrices M0,M1,M2

// ---------------------------------------------------------------------------
// Setup: a[v][w] = (adj[v][w] + I)/rowsum ;  fold alpha mixing into W
// ---------------------------------------------------------------------------
__global__ void mixprop_setup_kernel(const float* __restrict__ adj,
                                     const float* __restrict__ W)
{
    __shared__ float dinv[64];
    const int t = threadIdx.x;
    if (t < 64) {
        float s = 1.0f;                       // identity diagonal contribution
        #pragma unroll 8
        for (int w = 0; w < 64; ++w) s += adj[t * 64 + w];
        dinv[t] = 1.0f / s;
    }
    __syncthreads();
    for (int i = t; i < 4096; i += blockDim.x) {
        const int v = i >> 6, w = i & 63;
        float av = adj[i] + (v == w ? 1.0f : 0.0f);
        g_a[i] = av * dinv[v];
    }
    const float A = 0.05f, OMA = 0.95f;
    for (int i = t; i < 4096; i += blockDim.x) {
        const int o = i >> 6, c = i & 63;
        const float w0 = W[o * 192 + c];
        const float w1 = W[o * 192 + 64 + c];
        const float w2 = W[o * 192 + 128 + c];
        g_M[i]            = w0 + A * (w1 + w2);       // M0
        g_M[4096 + i]     = OMA * (w1 + A * w2);      // M1
        g_M[8192 + i]     = OMA * OMA * w2;           // M2
    }
}

// ---------------------------------------------------------------------------
// f32x2 helpers (packed dual-fp32 FMA — 2x FFMA throughput on sm_103a)
// ---------------------------------------------------------------------------
__device__ __forceinline__ u64 pack2(float s) {
    u64 r;
    asm("mov.b64 %0, {%1, %1};" : "=l"(r) : "f"(s));
    return r;
}
__device__ __forceinline__ void fma2(u64& d, u64 a, u64 b) {
    asm("fma.rn.f32x2 %0, %1, %2, %0;" : "+l"(d) : "l"(a), "l"(b));
}

// ---------------------------------------------------------------------------
// Channel GEMM: acc[o][(v,jp)] += M[o][c] * B[c][(v,jp)]   (row-contig B reads)
// thread tile: m = m0..m0+7 (o), n = tx + 32*i  i=0..3
// ---------------------------------------------------------------------------
__device__ __forceinline__ void gemmC(const float* __restrict__ Am,
                                      const float2* __restrict__ B,
                                      u64* acc, int m0, const int* nIdx)
{
    #pragma unroll 2
    for (int k2 = 0; k2 < 32; ++k2) {
        float2 af[8];
        #pragma unroll
        for (int im = 0; im < 8; ++im)
            af[im] = *(const float2*)(Am + (m0 + im) * 64 + k2 * 2);
        #pragma unroll
        for (int kk = 0; kk < 2; ++kk) {
            const int k = k2 * 2 + kk;
            u64 bb[4];
            #pragma unroll
            for (int i = 0; i < 4; ++i)
                bb[i] = *(const u64*)(B + k * PADC + nIdx[i]);
            #pragma unroll
            for (int im = 0; im < 8; ++im) {
                const u64 a2 = pack2(kk == 0 ? af[im].x : af[im].y);
                #pragma unroll
                for (int i = 0; i < 4; ++i)
                    fma2(acc[im * 4 + i], a2, bb[i]);
            }
        }
    }
}

// ---------------------------------------------------------------------------
// Vertex GEMM: y[v][(c,jp)] = sum_w a[v][w] * B[c][(w,jp)]  (transposed B reads)
// thread tile: m = m0..m0+7 (v), (c,jp) from cOff
// ---------------------------------------------------------------------------
__device__ __forceinline__ void gemmV(const float* __restrict__ Am,
                                      const float2* __restrict__ B,
                                      u64* acc, int m0, const int* cOff)
{
    #pragma unroll
    for (int j = 0; j < 32; ++j) acc[j] = 0ULL;
    #pragma unroll 2
    for (int k2 = 0; k2 < 32; ++k2) {
        float2 af[8];
        #pragma unroll
        for (int im = 0; im < 8; ++im)
            af[im] = *(const float2*)(Am + (m0 + im) * 64 + k2 * 2);
        #pragma unroll
        for (int kk = 0; kk < 2; ++kk) {
            const int k = k2 * 2 + kk;
            u64 bb[4];
            #pragma unroll
            for (int i = 0; i < 4; ++i)
                bb[i] = *(const u64*)(B + cOff[i] + k * 2);
            #pragma unroll
            for (int im = 0; im < 8; ++im) {
                const u64 a2 = pack2(kk == 0 ? af[im].x : af[im].y);
                #pragma unroll
                for (int i = 0; i < 4; ++i)
                    fma2(acc[im * 4 + i], a2, bb[i]);
            }
        }
    }
}

// store gemmV result y[v][(c,jp)] into buffer layout [c][(v,jp)]
__device__ __forceinline__ void storeY(float2* __restrict__ Bdst,
                                       const u64* acc, int m0, const int* cOff)
{
    #pragma unroll
    for (int im = 0; im < 8; ++im)
        #pragma unroll
        for (int i = 0; i < 4; ++i)
            *(u64*)(Bdst + cOff[i] + (m0 + im) * 2) = acc[im * 4 + i];
}

// ---------------------------------------------------------------------------
// Fused main kernel: one CTA = one (n, 8-l chunk); 2 slabs of 4 l each
// ---------------------------------------------------------------------------
__global__ void __launch_bounds__(256, 1)
mixprop_main_kernel(const float* __restrict__ x,
                    const float* __restrict__ bias,
                    float* __restrict__ out)
{
    extern __shared__ float smem[];
    float*  sA   = smem;                                   // 4096 floats
    float*  sM   = smem + 4096;                            // 12288 floats
    float2* sB0  = (float2*)(smem + SM_CONST_FLOATS);      // 8256 float2
    float2* sB1  = sB0 + BUF_F2;

    const int tid = threadIdx.x;

    // stage constant operators into smem (vectorized, fully covered)
    {
        float4*       dA = (float4*)sA;
        const float4* ga = (const float4*)g_a;
        #pragma unroll
        for (int i = 0; i < 4; ++i) dA[tid + 256 * i] = ga[tid + 256 * i];
        float4*       dM = (float4*)sM;
        const float4* gm = (const float4*)g_M;
        #pragma unroll
        for (int i = 0; i < 12; ++i) dM[tid + 256 * i] = gm[tid + 256 * i];
    }

    const int tx = tid & 31;
    const int ty = tid >> 5;
    const int m0 = ty * 8;

    int nIdx[4], cOff[4];
    #pragma unroll
    for (int i = 0; i < 4; ++i) {
        nIdx[i] = tx + 32 * i;                             // col = v*2 + jp (or c*2+jp)
        cOff[i] = (nIdx[i] >> 1) * PADC + (nIdx[i] & 1);   // transposed base offset
    }

    u64 bpack[8];
    #pragma unroll
    for (int im = 0; im < 8; ++im) bpack[im] = pack2(bias[m0 + im]);

    const int    n      = blockIdx.y;
    const size_t baseNC = (size_t)n * (NC * NV * LTOT);
    const float* xn     = x + baseNC;
    float*       outn   = out + baseNC;
    const int    l0base = blockIdx.x * 8;

    u64 outAcc[32], yAcc[32];

    __syncthreads();   // constants staged

    #pragma unroll 1
    for (int it = 0; it < 2; ++it) {
        const int l0 = l0base + it * 4;

        // Load X slab into sB0: layout [c][v*2+jp] of float2 (each float2 = l-pair)
        #pragma unroll
        for (int r = 0; r < 32; ++r) {
            const int idx = tid + 256 * r;
            const int c   = idx >> 7;
            const int col = idx & 127;
            const int v   = col >> 1;
            const int jp  = col & 1;
            const u64 val = *(const u64*)(xn + ((c * NV + v) * LTOT) + l0 + jp * 2);
            *(u64*)(sB0 + c * PADC + col) = val;
        }
        __syncthreads();

        // acc = b ;  acc += M0 * X ;  Y1 = A * X
        #pragma unroll
        for (int im = 0; im < 8; ++im)
            #pragma unroll
            for (int i = 0; i < 4; ++i)
                outAcc[im * 4 + i] = bpack[im];
        gemmC(sM, sB0, outAcc, m0, nIdx);
        gemmV(sA, sB0, yAcc, m0, cOff);
        storeY(sB1, yAcc, m0, cOff);
        __syncthreads();                       // Y1 visible; X reads finished

        // acc += M1 * Y1 ;  Y2 = A * Y1  (overwrite X buffer)
        gemmC(sM + 4096, sB1, outAcc, m0, nIdx);
        gemmV(sA, sB1, yAcc, m0, cOff);
        storeY(sB0, yAcc, m0, cOff);
        __syncthreads();                       // Y2 visible

        // acc += M2 * Y2 ;  write out
        gemmC(sM + 8192, sB0, outAcc, m0, nIdx);

        #pragma unroll
        for (int im = 0; im < 8; ++im) {
            const int o = m0 + im;
            #pragma unroll
            for (int i = 0; i < 4; ++i) {
                const int col = nIdx[i];
                const int v   = col >> 1;
                const int jp  = col & 1;
                *(u64*)(outn + ((o * NV + v) * LTOT) + l0 + jp * 2) = outAcc[im * 4 + i];
            }
        }
        __syncthreads();                       // protect sB0 before next slab load
    }
}

// ---------------------------------------------------------------------------
// Launch
// ---------------------------------------------------------------------------
extern "C" void kernel_launch(void* const* d_in, const int* in_sizes, int n_in,
                              void* d_out, int out_size)
{
    (void)in_sizes; (void)n_in; (void)out_size;
    const float* x   = (const float*)d_in[0];   // [32,64,64,512]
    const float* adj = (const float*)d_in[1];   // [64,64]
    const float* W   = (const float*)d_in[2];   // [64,192]
    const float* b   = (const float*)d_in[3];   // [64]
    float*       out = (float*)d_out;           // [32,64,64,512]

    mixprop_setup_kernel<<<1, 256>>>(adj, W);

    cudaFuncSetAttribute(mixprop_main_kernel,
                         cudaFuncAttributeMaxDynamicSharedMemorySize, SMEM_BYTES);

    dim3 grid(64, 32);   // 64 l-chunks (8 l each) x 32 batch
    mixprop_main_kernel<<<grid, 256, SMEM_BYTES>>>(x, b, out);
}